// round 15
// baseline (speedup 1.0000x reference)
#include <cuda_runtime.h>
#include <cstdint>
#include <math.h>

#define BB 64
#define LL 200
#define HH 128
#define SS 64
#define EE 256
#define NBLK 2
#define MM (BB*LL)
#define KC 101
#define LDSSM 192
#define LDXZ (2*EE)

// TF32 round-to-nearest (matches tensor-core operand conversion).
__device__ __forceinline__ float tf32r(float x) {
    float r;
    asm("cvt.rna.tf32.f32 %0, %1;" : "=f"(r) : "f"(x));
    return r;
}

__device__ __forceinline__ void mma_tf32(float c[4],
    uint32_t a0, uint32_t a1, uint32_t a2, uint32_t a3,
    uint32_t b0, uint32_t b1) {
    asm volatile(
        "mma.sync.aligned.m16n8k8.row.col.f32.tf32.tf32.f32 "
        "{%0,%1,%2,%3}, {%4,%5,%6,%7}, {%8,%9}, {%0,%1,%2,%3};\n"
        : "+f"(c[0]), "+f"(c[1]), "+f"(c[2]), "+f"(c[3])
        : "r"(a0), "r"(a1), "r"(a2), "r"(a3), "r"(b0), "r"(b1));
}

__device__ __forceinline__ float wredsum(float v) {
#pragma unroll
    for (int o = 16; o; o >>= 1) v += __shfl_xor_sync(0xffffffffu, v, o);
    return v;
}

// Scratch (device globals — no allocation allowed)
__device__ __align__(16) float g_x[MM*HH];
__device__ __align__(16) float g_u[MM*HH];
__device__ __align__(16) float g_xz[MM*LDXZ];
__device__ __align__(16) float g_xc[MM*EE];
__device__ __align__(16) float g_ssm[MM*LDSSM];   // [delta_raw | B_raw | C]
__device__ __align__(16) float g_y[MM*EE];
__device__ __align__(16) float g_xsum[MM];
__device__ __align__(16) float g_s[MM];

// ---------------------------------------------------------------------------
// Fused embed + first-block LN. Warp handles rows m and m+MM/2 (2x MLP).
__global__ void __launch_bounds__(256) embed_ln_kernel(
    const int* __restrict__ seqs,
    const float* __restrict__ item_emb, const float* __restrict__ pos_emb,
    const float* __restrict__ g, const float* __restrict__ b,
    float* __restrict__ x, float* __restrict__ u) {
    int warp = threadIdx.x >> 5, lane = threadIdx.x & 31;
    int mA = blockIdx.x * 8 + warp;
    int e = lane << 2;
    float4 gg = *(const float4*)(g + e);
    float4 bb = *(const float4*)(b + e);
#pragma unroll
    for (int rr = 0; rr < 2; rr++) {
        int m = mA + rr * (MM / 2);
        int l = m % LL;
        int id = seqs[m];
        float4 ie = *(const float4*)(item_emb + (size_t)id * HH + e);
        float4 pe = *(const float4*)(pos_emb + l * HH + e);
        float msk = (id != 0) ? 1.f : 0.f;
        float4 v;
        v.x = (ie.x + pe.x) * msk; v.y = (ie.y + pe.y) * msk;
        v.z = (ie.z + pe.z) * msk; v.w = (ie.w + pe.w) * msk;
        *(float4*)(x + (size_t)m * HH + e) = v;
        float mean = wredsum(v.x + v.y + v.z + v.w) * (1.f / HH);
        float4 d; d.x = v.x - mean; d.y = v.y - mean; d.z = v.z - mean; d.w = v.w - mean;
        float var = wredsum(d.x * d.x + d.y * d.y + d.z * d.z + d.w * d.w) * (1.f / HH);
        float inv = rsqrtf(var + 1e-5f);
        float4 o;
        o.x = d.x * inv * gg.x + bb.x; o.y = d.y * inv * gg.y + bb.y;
        o.z = d.z * inv * gg.z + bb.z; o.w = d.w * inv * gg.w + bb.w;
        *(float4*)(u + (size_t)m * HH + e) = o;
    }
}

// LayerNorm over H=128. Warp handles rows m and m+MM/2. Two-pass variance.
__global__ void __launch_bounds__(256) ln128_kernel(
    const float* __restrict__ x, float* __restrict__ u,
    const float* __restrict__ g, const float* __restrict__ b) {
    int warp = threadIdx.x >> 5, lane = threadIdx.x & 31;
    int mA = blockIdx.x * 8 + warp;
    int e = lane << 2;
    float4 v0 = *(const float4*)(x + (size_t)mA * HH + e);
    float4 v1 = *(const float4*)(x + (size_t)(mA + MM / 2) * HH + e);
    float4 gg = *(const float4*)(g + e);
    float4 bb = *(const float4*)(b + e);
#pragma unroll
    for (int rr = 0; rr < 2; rr++) {
        int m = mA + rr * (MM / 2);
        float4 v = rr ? v1 : v0;
        float mean = wredsum(v.x + v.y + v.z + v.w) * (1.f / HH);
        float4 d; d.x = v.x - mean; d.y = v.y - mean; d.z = v.z - mean; d.w = v.w - mean;
        float var = wredsum(d.x * d.x + d.y * d.y + d.z * d.z + d.w * d.w) * (1.f / HH);
        float inv = rsqrtf(var + 1e-5f);
        float4 o;
        o.x = d.x * inv * gg.x + bb.x; o.y = d.y * inv * gg.y + bb.y;
        o.z = d.z * inv * gg.z + bb.z; o.w = d.w * inv * gg.w + bb.w;
        *(float4*)(u + (size_t)m * HH + e) = o;
    }
}

// ---------------------------------------------------------------------------
// TF32 tensor-core GEMM (R11 proven config): BM=128, BN=64, BK=16; 8 warps.
// epi==1: C = (resid + C + bias) * mask (residual in C).
#define APAD 20
#define BPAD 72
__global__ void __launch_bounds__(256) gemm_tc_kernel(
    const float* __restrict__ A, int lda,
    const float* __restrict__ W, int ldw,
    const float* __restrict__ bias,
    float* __restrict__ C, int ldc,
    int Kdim, int epi, const int* __restrict__ seqs)
{
    __shared__ __align__(16) float As[2][128 * APAD];
    __shared__ __align__(16) float Ws[2][16 * BPAD];
    int tid = threadIdx.x;
    int m0 = blockIdx.y << 7, n0 = blockIdx.x << 6;
    int lane = tid & 31, wid = tid >> 5;
    int wm = (wid & 3) << 5;
    int wn = (wid >> 2) << 5;
    int g = lane >> 2, cq = lane & 3;

    int a_r = tid >> 2, a_q = tid & 3;
    int b_k = tid >> 4, b_q = tid & 15;
    const float* ApBase = A + (size_t)(m0 + a_r) * lda + (a_q << 2);
    const float* WpBase = W + (size_t)b_k * ldw + n0 + (b_q << 2);

    float acc[2][4][4];
#pragma unroll
    for (int i = 0; i < 2; i++)
#pragma unroll
        for (int j = 0; j < 4; j++)
#pragma unroll
            for (int q = 0; q < 4; q++) acc[i][j][q] = 0.f;

    float4 av0 = *(const float4*)(ApBase);
    float4 av1 = *(const float4*)(ApBase + (size_t)64 * lda);
    float4 bv  = *(const float4*)(WpBase);
    {
        float4 t0, t1, tb;
        t0.x = tf32r(av0.x); t0.y = tf32r(av0.y); t0.z = tf32r(av0.z); t0.w = tf32r(av0.w);
        t1.x = tf32r(av1.x); t1.y = tf32r(av1.y); t1.z = tf32r(av1.z); t1.w = tf32r(av1.w);
        tb.x = tf32r(bv.x);  tb.y = tf32r(bv.y);  tb.z = tf32r(bv.z);  tb.w = tf32r(bv.w);
        *(float4*)&As[0][a_r * APAD + (a_q << 2)] = t0;
        *(float4*)&As[0][(a_r + 64) * APAD + (a_q << 2)] = t1;
        *(float4*)&Ws[0][b_k * BPAD + (b_q << 2)] = tb;
    }
    __syncthreads();

    int nk = Kdim >> 4;
    for (int kt = 0; kt < nk; kt++) {
        int cur = kt & 1;
        if (kt + 1 < nk) {
            av0 = *(const float4*)(ApBase + ((kt + 1) << 4));
            av1 = *(const float4*)(ApBase + (size_t)64 * lda + ((kt + 1) << 4));
            bv  = *(const float4*)(WpBase + (size_t)((kt + 1) << 4) * ldw);
        }
#pragma unroll
        for (int ks = 0; ks < 2; ks++) {
            int kk = ks << 3;
            uint32_t bf[4][2];
#pragma unroll
            for (int j = 0; j < 4; j++) {
                bf[j][0] = __float_as_uint(Ws[cur][(kk + cq) * BPAD + wn + (j << 3) + g]);
                bf[j][1] = __float_as_uint(Ws[cur][(kk + cq + 4) * BPAD + wn + (j << 3) + g]);
            }
#pragma unroll
            for (int i = 0; i < 2; i++) {
                const float* ab = &As[cur][(wm + (i << 4)) * APAD + kk + cq];
                uint32_t a0 = __float_as_uint(ab[g * APAD]);
                uint32_t a1 = __float_as_uint(ab[(g + 8) * APAD]);
                uint32_t a2 = __float_as_uint(ab[g * APAD + 4]);
                uint32_t a3 = __float_as_uint(ab[(g + 8) * APAD + 4]);
#pragma unroll
                for (int j = 0; j < 4; j++)
                    mma_tf32(acc[i][j], a0, a1, a2, a3, bf[j][0], bf[j][1]);
            }
        }
        if (kt + 1 < nk) {
            int nxt = cur ^ 1;
            float4 t0, t1, tb;
            t0.x = tf32r(av0.x); t0.y = tf32r(av0.y); t0.z = tf32r(av0.z); t0.w = tf32r(av0.w);
            t1.x = tf32r(av1.x); t1.y = tf32r(av1.y); t1.z = tf32r(av1.z); t1.w = tf32r(av1.w);
            tb.x = tf32r(bv.x);  tb.y = tf32r(bv.y);  tb.z = tf32r(bv.z);  tb.w = tf32r(bv.w);
            *(float4*)&As[nxt][a_r * APAD + (a_q << 2)] = t0;
            *(float4*)&As[nxt][(a_r + 64) * APAD + (a_q << 2)] = t1;
            *(float4*)&Ws[nxt][b_k * BPAD + (b_q << 2)] = tb;
        }
        __syncthreads();
    }

#pragma unroll
    for (int i = 0; i < 2; i++) {
        int r0 = m0 + wm + (i << 4) + g;
        int r1 = r0 + 8;
        float msk0 = 1.f, msk1 = 1.f;
        if (epi == 1) {
            msk0 = (seqs[r0] != 0) ? 1.f : 0.f;
            msk1 = (seqs[r1] != 0) ? 1.f : 0.f;
        }
#pragma unroll
        for (int j = 0; j < 4; j++) {
            int col = n0 + wn + (j << 3) + (cq << 1);
            float b0 = bias[col], b1 = bias[col + 1];
            size_t o0 = (size_t)r0 * ldc + col;
            size_t o1 = (size_t)r1 * ldc + col;
            float v00 = acc[i][j][0] + b0, v01 = acc[i][j][1] + b1;
            float v10 = acc[i][j][2] + b0, v11 = acc[i][j][3] + b1;
            if (epi == 1) {
                v00 = (C[o0] + v00) * msk0; v01 = (C[o0 + 1] + v01) * msk0;
                v10 = (C[o1] + v10) * msk1; v11 = (C[o1 + 1] + v11) * msk1;
            }
            C[o0] = v00; C[o0 + 1] = v01;
            C[o1] = v10; C[o1 + 1] = v11;
        }
    }
}

// depthwise conv k=3 pad (1,1) + silu + row-sum. Warp handles 2 rows;
// conv weights/bias hoisted into registers across rows.
__global__ void __launch_bounds__(256) conv_kernel(
    const float* __restrict__ xz,
    const float* __restrict__ cw, const float* __restrict__ cb,
    float* __restrict__ xc, float* __restrict__ xsum) {
    int warp = threadIdx.x >> 5, lane = threadIdx.x & 31;
    int mA = blockIdx.x * 8 + warp;
    float w0[8], w1[8], w2[8], cbv[8];
#pragma unroll
    for (int h = 0; h < 2; h++) {
        int e = (lane << 3) + (h << 2);
        float4 cb4 = *(const float4*)(cb + e);
        cbv[h*4+0] = cb4.x; cbv[h*4+1] = cb4.y; cbv[h*4+2] = cb4.z; cbv[h*4+3] = cb4.w;
#pragma unroll
        for (int j = 0; j < 4; j++) {
            int ee = e + j;
            w0[h*4+j] = tf32r(cw[ee * 3 + 0]);
            w1[h*4+j] = tf32r(cw[ee * 3 + 1]);
            w2[h*4+j] = tf32r(cw[ee * 3 + 2]);
        }
    }
#pragma unroll
    for (int rr = 0; rr < 2; rr++) {
        int m = mA + rr * (MM / 2);
        int l = m % LL;
        const float* xr = xz + (size_t)m * LDXZ;
        float s = 0.f;
#pragma unroll
        for (int h = 0; h < 2; h++) {
            int e = (lane << 3) + (h << 2);
            float4 vm = *(const float4*)(xr + e);
            float4 vl = (l > 0) ? *(const float4*)(xr - LDXZ + e) : make_float4(0.f, 0.f, 0.f, 0.f);
            float4 vh = (l < LL - 1) ? *(const float4*)(xr + LDXZ + e) : make_float4(0.f, 0.f, 0.f, 0.f);
            float am[4] = {vm.x, vm.y, vm.z, vm.w};
            float al[4] = {vl.x, vl.y, vl.z, vl.w};
            float ah[4] = {vh.x, vh.y, vh.z, vh.w};
            float out[4];
#pragma unroll
            for (int j = 0; j < 4; j++) {
                int q = h * 4 + j;
                float acc = tf32r(am[j]) * w1[q];
                acc += tf32r(al[j]) * w0[q];
                acc += tf32r(ah[j]) * w2[q];
                acc += cbv[q];
                float sv = acc / (1.f + __expf(-acc));
                out[j] = sv;
                s += sv;
            }
            *(float4*)(xc + (size_t)m * EE + e) = make_float4(out[0], out[1], out[2], out[3]);
        }
        s = wredsum(s);
        if (lane == 0) xsum[m] = s;
    }
}

// Sequential scan, software-pipelined: step t+1's exps (MUFU) are issued before
// step t's serial matvec chain — exponentials depend only on delta, not on the
// recurrence state, so they overlap. Emit partials go to psumAll; summed after
// the loop (removes per-step tid0 sum from the critical path).
__global__ void __launch_bounds__(256) scan_kernel(
    const float* __restrict__ ssm, const float* __restrict__ xsum,
    const float* __restrict__ A_log, float* __restrict__ sout, int lastonly)
{
    int b = blockIdx.x, tid = threadIdx.x;
    __shared__ float A_sh[SS];
    __shared__ __align__(16) float gbuf[2][SS];
    __shared__ float psumAll[LL * 8];
    if (tid < SS) {
        float al = A_log[tid];
        al = fminf(fmaxf(al, -5.f), 5.f);
        A_sh[tid] = -expf(al) * 1.44269504088896340736f;   // A * log2(e)
        gbuf[0][tid] = 0.f;
    }
    __syncthreads();
    int i = tid >> 2, sub = tid & 3;
    int warp = tid >> 5;
    float Aj[16];
#pragma unroll
    for (int q = 0; q < 16; q++) Aj[q] = A_sh[sub * 16 + q];

    const float* row = ssm + (size_t)b * LL * LDSSM;
    const float* xsr = xsum + b * LL;
    const float CLMP = -14.4269504088896340736f;           // -10*log2(e)

    // step-0 data + exps
    float ex[16];
    float db, Cv, xs;
    {
        float draw = row[i];
        float d = fmaxf(draw, 0.f) + log1pf(__expf(-fabsf(draw)));
        db = d * row[SS + i]; Cv = row[2 * SS + i]; xs = xsr[0];
#pragma unroll
        for (int q = 0; q < 16; q++)
            ex[q] = tf32r(exp2f(fmaxf(d * Aj[q], CLMP)));
    }
    // raws for step 1
    float nd = 0, nbm = 0, nC = 0, nxs = 0;
    if (LL > 1) { nd = row[LDSSM + i]; nbm = row[LDSSM + SS + i];
                  nC = row[LDSSM + 2 * SS + i]; nxs = xsr[1]; }

    for (int t = 0; t < LL; t++) {
        // 1) exps for t+1 (independent of recurrence — fills MUFU early)
        float exn[16], dbn = 0, Cn = 0, xsn = 0;
        if (t + 1 < LL) {
            float d = fmaxf(nd, 0.f) + log1pf(__expf(-fabsf(nd)));
            dbn = d * nbm; Cn = nC; xsn = nxs;
#pragma unroll
            for (int q = 0; q < 16; q++)
                exn[q] = tf32r(exp2f(fmaxf(d * Aj[q], CLMP)));
        }
        // 2) prefetch raws for t+2
        if (t + 2 < LL) {
            const float* r2 = row + (t + 2) * LDSSM;
            nd = r2[i]; nbm = r2[SS + i]; nC = r2[2 * SS + i]; nxs = xsr[t + 2];
        }
        // 3) serial matvec for step t (uses ex computed last iteration)
        int par = t & 1;
        const float4* g4 = (const float4*)(gbuf[par] + sub * 16);
        float acc = 0.f;
#pragma unroll
        for (int q4 = 0; q4 < 4; q4++) {
            float4 gv = g4[q4];
            acc += ex[q4 * 4 + 0] * gv.x;
            acc += ex[q4 * 4 + 1] * gv.y;
            acc += ex[q4 * 4 + 2] * gv.z;
            acc += ex[q4 * 4 + 3] * gv.w;
        }
        acc += __shfl_xor_sync(0xffffffffu, acc, 1);
        acc += __shfl_xor_sync(0xffffffffu, acc, 2);
        if (sub == 0) {
            float gn = acc + db * xs;
            gn = fminf(fmaxf(gn, -100.f), 100.f);
            float gr = tf32r(gn);
            gbuf[par ^ 1][i] = gr;
            if ((!lastonly) || (t == LL - 1)) {
                float p = gr * tf32r(Cv);
                p += __shfl_xor_sync(0x11111111u, p, 4);
                p += __shfl_xor_sync(0x11111111u, p, 8);
                p += __shfl_xor_sync(0x11111111u, p, 16);
                if ((tid & 31) == 0) psumAll[t * 8 + warp] = p;
            }
        }
        __syncthreads();
        // rotate pipeline registers
#pragma unroll
        for (int q = 0; q < 16; q++) ex[q] = exn[q];
        db = dbn; Cv = Cn; xs = xsn;
    }

    // bulk emit-sum
    for (int t = tid; t < LL; t += 256) {
        if (lastonly && t != LL - 1) continue;
        float t2 = 0.f;
#pragma unroll
        for (int w = 0; w < 8; w++) t2 += psumAll[t * 8 + w];
        sout[b * LL + t] = t2;
    }
}

// y = s + D*x ; inner LN over E (two-pass); y *= silu(z). Warp handles 2 rows;
// D/gamma/beta hoisted across rows.
__global__ void __launch_bounds__(256) act_kernel(
    const float* __restrict__ xc, const float* __restrict__ s_in,
    const float* __restrict__ xz, const float* __restrict__ D,
    const float* __restrict__ ig, const float* __restrict__ ib,
    float* __restrict__ y, int lastonly, int halfstride) {
    int warp = threadIdx.x >> 5, lane = threadIdx.x & 31;
    int rA = blockIdx.x * 8 + warp;
    float4 dv[2], gv[2], bv[2];
#pragma unroll
    for (int h = 0; h < 2; h++) {
        int e = (lane << 3) + (h << 2);
        dv[h] = *(const float4*)(D + e);
        gv[h] = *(const float4*)(ig + e);
        bv[h] = *(const float4*)(ib + e);
    }
#pragma unroll
    for (int rr = 0; rr < 2; rr++) {
        int r = rA + rr * halfstride;
        int m = lastonly ? (r * LL + (LL - 1)) : r;
        float sv = s_in[m];
        const float* xcr = xc + (size_t)m * EE;
        float yv[8];
        float tot = 0.f;
#pragma unroll
        for (int h = 0; h < 2; h++) {
            int e = (lane << 3) + (h << 2);
            float4 xv = *(const float4*)(xcr + e);
            yv[h * 4 + 0] = sv + dv[h].x * xv.x; yv[h * 4 + 1] = sv + dv[h].y * xv.y;
            yv[h * 4 + 2] = sv + dv[h].z * xv.z; yv[h * 4 + 3] = sv + dv[h].w * xv.w;
            tot += yv[h * 4 + 0] + yv[h * 4 + 1] + yv[h * 4 + 2] + yv[h * 4 + 3];
        }
        float mean = wredsum(tot) * (1.f / EE);
        float vs = 0.f;
#pragma unroll
        for (int q = 0; q < 8; q++) { yv[q] -= mean; vs += yv[q] * yv[q]; }
        float var = wredsum(vs) * (1.f / EE);
        float inv = rsqrtf(var + 1e-5f);
        const float* zr = xz + (size_t)m * LDXZ + EE;
#pragma unroll
        for (int h = 0; h < 2; h++) {
            int e = (lane << 3) + (h << 2);
            float4 zv = *(const float4*)(zr + e);
            float4 o;
            o.x = (yv[h*4+0] * inv * gv[h].x + bv[h].x) * (zv.x / (1.f + __expf(-zv.x)));
            o.y = (yv[h*4+1] * inv * gv[h].y + bv[h].y) * (zv.y / (1.f + __expf(-zv.y)));
            o.z = (yv[h*4+2] * inv * gv[h].z + bv[h].z) * (zv.z / (1.f + __expf(-zv.z)));
            o.w = (yv[h*4+3] * inv * gv[h].w + bv[h].w) * (zv.w / (1.f + __expf(-zv.w)));
            *(float4*)(y + (size_t)m * EE + e) = o;
        }
    }
}

// Merged last-timestep projections (block 1): blockIdx.y selects job.
// job 0: z-half of in-proj; job 1: C-cols of x-proj.
__global__ void lastproj2_kernel(
    const float* __restrict__ A0, int lda0, const float* __restrict__ W0, int ldw0,
    const float* __restrict__ bias0, float* __restrict__ C0, int ldc0,
    int Kdim0, int ncols0, int coloff0,
    const float* __restrict__ A1, int lda1, const float* __restrict__ W1, int ldw1,
    const float* __restrict__ bias1, float* __restrict__ C1, int ldc1,
    int Kdim1, int ncols1, int coloff1) {
    int b = blockIdx.x;
    int row = b * LL + (LL - 1);
    const float* A; int lda; const float* W; int ldw; const float* bias;
    float* C; int ldc, Kdim, ncols, coloff;
    if (blockIdx.y == 0) { A = A0; lda = lda0; W = W0; ldw = ldw0; bias = bias0;
                           C = C0; ldc = ldc0; Kdim = Kdim0; ncols = ncols0; coloff = coloff0; }
    else                 { A = A1; lda = lda1; W = W1; ldw = ldw1; bias = bias1;
                           C = C1; ldc = ldc1; Kdim = Kdim1; ncols = ncols1; coloff = coloff1; }
    __shared__ float ush[EE];
    int tid = threadIdx.x;
    if (tid < Kdim) ush[tid] = tf32r(A[(size_t)row * lda + tid]);
    __syncthreads();
    for (int n = tid; n < ncols; n += blockDim.x) {
        float acc = 0.f;
        const float* wp = W + coloff + n;
#pragma unroll 4
        for (int k = 0; k < Kdim; k++) acc += ush[k] * tf32r(wp[(size_t)k * ldw]);
        C[(size_t)row * ldc + coloff + n] = acc + bias[coloff + n];
    }
}

// out-proj + residual + mask for last-timestep rows (block 2)
__global__ void lastout_kernel(const float* __restrict__ y, const float* __restrict__ ow,
                               const float* __restrict__ ob, const int* __restrict__ seqs,
                               float* __restrict__ x) {
    int b = blockIdx.x, h = threadIdx.x;   // 128 threads
    int row = b * LL + (LL - 1);
    __shared__ float ysh[EE];
    ysh[h] = tf32r(y[(size_t)row * EE + h]);
    ysh[h + HH] = tf32r(y[(size_t)row * EE + h + HH]);
    __syncthreads();
    float acc = 0.f;
#pragma unroll 4
    for (int e = 0; e < EE; e++) acc += ysh[e] * tf32r(ow[e * HH + h]);
    float v = x[(size_t)row * HH + h] + (acc + ob[h]);
    x[(size_t)row * HH + h] = (seqs[row] != 0) ? v : 0.f;
}

// final LN (last timestep only, two-pass) + logits vs candidates (tf32 dot)
__global__ void final_kernel(const float* __restrict__ x, const int* __restrict__ idxs,
                             const float* __restrict__ item_emb,
                             const float* __restrict__ fg, const float* __restrict__ fb,
                             float* __restrict__ out) {
    int b = blockIdx.x, tid = threadIdx.x;   // 128 threads
    const float* xr = x + (size_t)(b * LL + LL - 1) * HH;
    float v = xr[tid];
    __shared__ float sh1[4], sh2[4];
    float s1 = v;
#pragma unroll
    for (int o = 16; o; o >>= 1) s1 += __shfl_xor_sync(0xffffffffu, s1, o);
    if ((tid & 31) == 0) sh1[tid >> 5] = s1;
    __syncthreads();
    float mean = (sh1[0] + sh1[1] + sh1[2] + sh1[3]) * (1.f / HH);
    float d = v - mean;
    float s2 = d * d;
#pragma unroll
    for (int o = 16; o; o >>= 1) s2 += __shfl_xor_sync(0xffffffffu, s2, o);
    if ((tid & 31) == 0) sh2[tid >> 5] = s2;
    __syncthreads();
    float var = (sh2[0] + sh2[1] + sh2[2] + sh2[3]) * (1.f / HH);
    __shared__ float xn[HH];
    xn[tid] = tf32r(d * rsqrtf(var + 1e-5f) * fg[tid] + fb[tid]);
    __syncthreads();
    int warp = tid >> 5, lane = tid & 31;
    for (int k = warp; k < KC; k += 4) {
        const float* er = item_emb + (size_t)idxs[b * KC + k] * HH;
        float p = xn[lane] * tf32r(er[lane]) + xn[lane + 32] * tf32r(er[lane + 32])
                + xn[lane + 64] * tf32r(er[lane + 64]) + xn[lane + 96] * tf32r(er[lane + 96]);
#pragma unroll
        for (int o = 16; o; o >>= 1) p += __shfl_xor_sync(0xffffffffu, p, o);
        if (lane == 0) out[b * KC + k] = p;
    }
}

// ---------------------------------------------------------------------------
extern "C" void kernel_launch(void* const* d_in, const int* in_sizes, int n_in,
                              void* d_out, int out_size) {
    (void)in_sizes; (void)n_in; (void)out_size;
    const int*   seqs     = (const int*)d_in[0];
    const int*   idxs     = (const int*)d_in[1];
    const float* item_emb = (const float*)d_in[2];
    const float* pos_emb  = (const float*)d_in[3];
    const float* blk_ln_g = (const float*)d_in[4];
    const float* blk_ln_b = (const float*)d_in[5];
    const float* in_w     = (const float*)d_in[6];
    const float* in_b     = (const float*)d_in[7];
    const float* conv_w   = (const float*)d_in[8];
    const float* conv_b   = (const float*)d_in[9];
    const float* xproj_w  = (const float*)d_in[10];
    const float* xproj_b  = (const float*)d_in[11];
    const float* A_log    = (const float*)d_in[12];
    const float* D_param  = (const float*)d_in[13];
    const float* out_w    = (const float*)d_in[14];
    const float* out_b    = (const float*)d_in[15];
    const float* inner_g  = (const float*)d_in[16];
    const float* inner_b  = (const float*)d_in[17];
    const float* final_g  = (const float*)d_in[18];
    const float* final_b  = (const float*)d_in[19];
    float* outp = (float*)d_out;

    float *px, *pu, *pxz, *pxc, *pssm, *py, *pxsum, *ps;
    cudaGetSymbolAddress((void**)&px, g_x);
    cudaGetSymbolAddress((void**)&pu, g_u);
    cudaGetSymbolAddress((void**)&pxz, g_xz);
    cudaGetSymbolAddress((void**)&pxc, g_xc);
    cudaGetSymbolAddress((void**)&pssm, g_ssm);
    cudaGetSymbolAddress((void**)&py, g_y);
    cudaGetSymbolAddress((void**)&pxsum, g_xsum);
    cudaGetSymbolAddress((void**)&ps, g_s);

    for (int blk = 0; blk < NBLK; blk++) {
        const float* iw  = in_w    + (size_t)blk * HH * 2 * EE;
        const float* ibb = in_b    + blk * 2 * EE;
        const float* cw  = conv_w  + blk * EE * 3;
        const float* cb  = conv_b  + blk * EE;
        const float* xw  = xproj_w + (size_t)blk * EE * 3 * SS;
        const float* xb  = xproj_b + blk * 3 * SS;
        const float* al  = A_log   + blk * SS;
        const float* dp  = D_param + blk * EE;
        const float* ow  = out_w   + (size_t)blk * EE * HH;
        const float* ob  = out_b   + blk * HH;
        const float* ig  = inner_g + blk * EE;
        const float* ibn = inner_b + blk * EE;

        if (blk == 0)
            embed_ln_kernel<<<MM / 16, 256>>>(seqs, item_emb, pos_emb,
                                              blk_ln_g, blk_ln_b, px, pu);
        else
            ln128_kernel<<<MM / 16, 256>>>(px, pu, blk_ln_g + blk * HH,
                                           blk_ln_b + blk * HH);

        int Nin = (blk == 0) ? (2 * EE) : EE;
        gemm_tc_kernel<<<dim3(Nin / 64, MM / 128), 256>>>(pu, HH, iw, 2 * EE, ibb,
                                                          pxz, 2 * EE, HH, 0, nullptr);

        conv_kernel<<<MM / 16, 256>>>(pxz, cw, cb, pxc, pxsum);

        int Nxp = (blk == 0) ? (3 * SS) : (2 * SS);
        gemm_tc_kernel<<<dim3(Nxp / 64, MM / 128), 256>>>(pxc, EE, xw, 3 * SS, xb,
                                                          pssm, LDSSM, EE, 0, nullptr);
        if (blk == 1)
            lastproj2_kernel<<<dim3(BB, 2), 256>>>(
                pu, HH, iw, 2 * EE, ibb, pxz, 2 * EE, HH, EE, EE,
                pxc, EE, xw, 3 * SS, xb, pssm, LDSSM, EE, SS, 2 * SS);

        scan_kernel<<<BB, 256>>>(pssm, pxsum, al, ps, (blk == 1) ? 1 : 0);

        if (blk == 0) {
            act_kernel<<<MM / 16, 256>>>(pxc, ps, pxz, dp, ig, ibn, py, 0, MM / 2);
            gemm_tc_kernel<<<dim3(HH / 64, MM / 128), 256>>>(py, EE, ow, HH, ob,
                                                             px, HH, EE, 1, seqs);
        } else {
            act_kernel<<<BB / 16, 256>>>(pxc, ps, pxz, dp, ig, ibn, py, 1, BB / 2);
            lastout_kernel<<<BB, HH>>>(py, ow, ob, seqs, px);
        }
    }

    final_kernel<<<BB, HH>>>(px, idxs, item_emb, final_g, final_b, outp);
}